// round 7
// baseline (speedup 1.0000x reference)
#include <cuda_runtime.h>
#include <cuda_fp16.h>
#include <math.h>

#define N_NODES 50000
#define N_EDGES 800000
#define MM1_BLOCKS ((N_NODES + 63) / 64)           // 782
#define CNT_BLOCKS ((N_EDGES + 255) / 256)         // 3125

// Scratch (device globals — allocation-free per harness rules)
__device__ int   g_degi[N_NODES];
__device__ int   g_off[N_NODES];
__device__ int   g_cursor[N_NODES];
__device__ int   g_bsum[64];
__device__ int   g_esrc[N_EDGES];       // CSR payload: src node of each in-edge of n
__device__ float g_dinv[N_NODES];
__device__ __align__(16) __half g_th[N_NODES * 64];   // t = x @ W1 (fp16)
__device__ __align__(16) float  g_agg[N_NODES * 64];  // normalized aggregation
__device__ __align__(16) __half g_Ph[N_NODES * 128];  // [A | B] per-node precompute (fp16)

// ---- packed f32x2 helpers (sm_103a FFMA2 — ptxas never auto-fuses these) ----
typedef unsigned long long ull;
__device__ __forceinline__ ull pack2(float v) {
    ull r; asm("mov.b64 %0, {%1,%2};" : "=l"(r) : "f"(v), "f"(v)); return r;
}
__device__ __forceinline__ ull packf2(float2 f) {
    ull r; asm("mov.b64 %0, {%1,%2};" : "=l"(r) : "f"(f.x), "f"(f.y)); return r;
}
__device__ __forceinline__ void unpack2(ull v, float& lo, float& hi) {
    asm("mov.b64 {%0,%1}, %2;" : "=f"(lo), "=f"(hi) : "l"(v));
}
__device__ __forceinline__ void fma2(ull& d, ull a, ull b) {
    asm("fma.rn.f32x2 %0, %1, %2, %0;" : "+l"(d) : "l"(a), "l"(b));
}
__device__ __forceinline__ ull add2(ull a, ull b) {
    ull r; asm("add.rn.f32x2 %0, %1, %2;" : "=l"(r) : "l"(a), "l"(b)); return r;
}
__device__ __forceinline__ unsigned int hadd2(unsigned int a, unsigned int b) {
    unsigned int r; asm("add.rn.f16x2 %0, %1, %2;" : "=r"(r) : "r"(a), "r"(b)); return r;
}
__device__ __forceinline__ ull h2tof2(unsigned int h) {
    __half2 hv = *reinterpret_cast<__half2*>(&h);
    float2 f = __half22float2(hv);
    return packf2(f);
}
__device__ __forceinline__ unsigned int f2h2(float lo, float hi) {
    __half2 p = __floats2half2_rn(lo, hi);
    return *(unsigned int*)&p;
}

__global__ void k_zero() {
    int i = blockIdx.x * blockDim.x + threadIdx.x;
    if (i < N_NODES) g_degi[i] = 0;
}

// ---- exclusive prefix scan over g_degi (50000) -> g_off ----
__global__ void k_scan1() {
    int tid = threadIdx.x;
    int i = blockIdx.x * 1024 + tid;
    int v = (i < N_NODES) ? g_degi[i] : 0;
    int lane = tid & 31, wid = tid >> 5;
    int s = v;
#pragma unroll
    for (int o = 1; o < 32; o <<= 1) {
        int t = __shfl_up_sync(0xffffffffu, s, o);
        if (lane >= o) s += t;
    }
    __shared__ int ws[32];
    if (lane == 31) ws[wid] = s;
    __syncthreads();
    if (wid == 0) {
        int t = ws[lane];
        int ss = t;
#pragma unroll
        for (int o = 1; o < 32; o <<= 1) {
            int u = __shfl_up_sync(0xffffffffu, ss, o);
            if (lane >= o) ss += u;
        }
        ws[lane] = ss - t;
    }
    __syncthreads();
    int excl = ws[wid] + s - v;
    if (i < N_NODES) g_off[i] = excl;
    if (tid == 1023) g_bsum[blockIdx.x] = ws[31] + s;
}

// scan3: per-block base via redundant smem sum; init cursor; dinv (incl. self loop)
__global__ void k_scan3(int nb) {
    __shared__ int sb[64];
    __shared__ int base_s;
    int tid = threadIdx.x;
    if (tid < 64) sb[tid] = (tid < nb) ? g_bsum[tid] : 0;
    __syncthreads();
    if (tid == 0) {
        int b = 0;
        for (int j = 0; j < (int)blockIdx.x; j++) b += sb[j];
        base_s = b;
    }
    __syncthreads();
    int i = blockIdx.x * 1024 + tid;
    if (i >= N_NODES) return;
    int o = g_off[i] + base_s;
    g_off[i] = o;
    g_cursor[i] = o;
    g_dinv[i] = rsqrtf((float)(g_degi[i] + 1));
}

// CSR fill: store src id directly
__global__ void k_fill(const int* __restrict__ src, const int* __restrict__ dst) {
    int e = blockIdx.x * blockDim.x + threadIdx.x;
    if (e >= N_EDGES) return;
    int pos = atomicAdd(&g_cursor[dst[e]], 1);
    g_esrc[pos] = src[e];
}

// Fused: blocks [0, MM1_BLOCKS) compute t = x @ W1 (fp16 out);
//        blocks [MM1_BLOCKS, ...) do degree counting (independent work, overlaps).
__global__ void k_mm1cnt(const float* __restrict__ x, const float* __restrict__ W1,
                         const int* __restrict__ dst) {
    __shared__ float sW[64 * 64];        // [k][j]
    __shared__ float sx[64 * 68];        // row-major [r][k], pitch 68 floats
    int tid = threadIdx.x;
    if (blockIdx.x >= MM1_BLOCKS) {      // ---- degree count path ----
        int e = (blockIdx.x - MM1_BLOCKS) * 256 + tid;
        if (e < N_EDGES) atomicAdd(&g_degi[dst[e]], 1);
        return;
    }
    int row0 = blockIdx.x * 64;
    const float4* W4 = (const float4*)W1;
    float4* sW4s = (float4*)sW;
    for (int i = tid; i < 1024; i += 256) sW4s[i] = W4[i];
    const float4* x4 = (const float4*)x;
    float4* sx4 = (float4*)sx;
    for (int i = tid; i < 1024; i += 256) {
        int r = i >> 4, q = i & 15;
        int row = row0 + r;
        float4 v = (row < N_NODES) ? x4[row * 16 + q] : make_float4(0.f, 0.f, 0.f, 0.f);
        sx4[r * 17 + q] = v;
    }
    __syncthreads();
    int ty = tid >> 4, tx = tid & 15;
    ull c0a = 0, c0b = 0, c1a = 0, c1b = 0, c2a = 0, c2b = 0, c3a = 0, c3b = 0;
    const ulonglong2* sWu = (const ulonglong2*)sW;
    int rb = ty * 4;
#pragma unroll
    for (int k4 = 0; k4 < 16; k4++) {
        float4 xv0 = *(const float4*)&sx[(rb + 0) * 68 + k4 * 4];
        float4 xv1 = *(const float4*)&sx[(rb + 1) * 68 + k4 * 4];
        float4 xv2 = *(const float4*)&sx[(rb + 2) * 68 + k4 * 4];
        float4 xv3 = *(const float4*)&sx[(rb + 3) * 68 + k4 * 4];
        const float* p0 = &xv0.x;
        const float* p1 = &xv1.x;
        const float* p2 = &xv2.x;
        const float* p3 = &xv3.x;
#pragma unroll
        for (int j = 0; j < 4; j++) {
            int k = k4 * 4 + j;
            ulonglong2 w = sWu[k * 16 + tx];
            ull X0 = pack2(p0[j]), X1 = pack2(p1[j]), X2 = pack2(p2[j]), X3 = pack2(p3[j]);
            fma2(c0a, X0, w.x); fma2(c0b, X0, w.y);
            fma2(c1a, X1, w.x); fma2(c1b, X1, w.y);
            fma2(c2a, X2, w.x); fma2(c2b, X2, w.y);
            fma2(c3a, X3, w.x); fma2(c3b, X3, w.y);
        }
    }
    uint2* th2 = (uint2*)g_th;   // 16 uint2 per node row (64 halves)
    int row = row0 + rb;
    float lo, hi;
    uint2 u;
    unpack2(c0a, lo, hi); u.x = f2h2(lo, hi);
    unpack2(c0b, lo, hi); u.y = f2h2(lo, hi);
    if (row + 0 < N_NODES) th2[(row + 0) * 16 + tx] = u;
    unpack2(c1a, lo, hi); u.x = f2h2(lo, hi);
    unpack2(c1b, lo, hi); u.y = f2h2(lo, hi);
    if (row + 1 < N_NODES) th2[(row + 1) * 16 + tx] = u;
    unpack2(c2a, lo, hi); u.x = f2h2(lo, hi);
    unpack2(c2b, lo, hi); u.y = f2h2(lo, hi);
    if (row + 2 < N_NODES) th2[(row + 2) * 16 + tx] = u;
    unpack2(c3a, lo, hi); u.x = f2h2(lo, hi);
    unpack2(c3b, lo, hi); u.y = f2h2(lo, hi);
    if (row + 3 < N_NODES) th2[(row + 3) * 16 + tx] = u;
}

// CSR gather-reduce over fp16 t, no atomics. 8 threads/node, uint4 (8 cols) each.
__global__ void k_agg() {
    unsigned int gid = blockIdx.x * blockDim.x + threadIdx.x;
    unsigned int n = gid >> 3;
    int c = gid & 7;
    if (n >= N_NODES) return;
    const uint4* t4 = (const uint4*)g_th;   // 8 uint4 per node row
    float dn = g_dinv[n];
    uint4 u = t4[n * 8 + c];
    ull w2 = pack2(dn * dn);
    ull acc0 = 0, acc1 = 0, acc2 = 0, acc3 = 0;
    fma2(acc0, h2tof2(u.x), w2);
    fma2(acc1, h2tof2(u.y), w2);
    fma2(acc2, h2tof2(u.z), w2);
    fma2(acc3, h2tof2(u.w), w2);
    int beg = g_off[n];
    int end = beg + g_degi[n];
#pragma unroll 4
    for (int j = beg; j < end; j++) {
        int s = g_esrc[j];             // broadcast across the 8-thread group
        ull w = pack2(dn * g_dinv[s]);
        uint4 uu = t4[s * 8 + c];
        fma2(acc0, h2tof2(uu.x), w);
        fma2(acc1, h2tof2(uu.y), w);
        fma2(acc2, h2tof2(uu.z), w);
        fma2(acc3, h2tof2(uu.w), w);
    }
    float4* agg4 = (float4*)g_agg;      // 16 float4 per node row; thread owns 2
    float a, b, cc, d;
    unpack2(acc0, a, b); unpack2(acc1, cc, d);
    agg4[n * 16 + c * 2 + 0] = make_float4(a, b, cc, d);
    unpack2(acc2, a, b); unpack2(acc3, cc, d);
    agg4[n * 16 + c * 2 + 1] = make_float4(a, b, cc, d);
}

// h = relu(agg + b1); P = [h@Wm1[0:64]+bm1 | h@Wm1[64:128]] stored fp16
__global__ void k_mm2(const float* __restrict__ Wm1, const float* __restrict__ b1,
                      const float* __restrict__ bm1) {
    __shared__ float sW[64 * 128];  // [k][0:64]=Wm1[k], [k][64:128]=Wm1[64+k]
    __shared__ float sh[64 * 68];   // row-major [r][k], pitch 68
    int tid = threadIdx.x;
    int row0 = blockIdx.x * 64;
    const float4* Wm14 = (const float4*)Wm1;
    float4* sW4s = (float4*)sW;
    for (int i = tid; i < 2048; i += 256) {
        int k = i >> 5, jq = i & 31;
        float4 v = (jq < 16) ? Wm14[k * 16 + jq] : Wm14[(64 + k) * 16 + (jq - 16)];
        sW4s[i] = v;
    }
    const float4* agg4 = (const float4*)g_agg;
    const float4* b14 = (const float4*)b1;
    float4* sh4 = (float4*)sh;
    for (int i = tid; i < 1024; i += 256) {
        int r = i >> 4, q = i & 15;
        int row = row0 + r;
        float4 v = make_float4(0.f, 0.f, 0.f, 0.f);
        if (row < N_NODES) {
            float4 a = agg4[row * 16 + q];
            float4 b = b14[q];
            v.x = fmaxf(a.x + b.x, 0.f); v.y = fmaxf(a.y + b.y, 0.f);
            v.z = fmaxf(a.z + b.z, 0.f); v.w = fmaxf(a.w + b.w, 0.f);
        }
        sh4[r * 17 + q] = v;
    }
    __syncthreads();
    int ty = tid >> 4, tx = tid & 15;
    ull a0[4] = {0,0,0,0}, a1[4] = {0,0,0,0}, a2[4] = {0,0,0,0}, a3[4] = {0,0,0,0};
    const ulonglong2* sWu = (const ulonglong2*)sW;
    int rb = ty * 4;
#pragma unroll
    for (int k4 = 0; k4 < 16; k4++) {
        float4 hv0 = *(const float4*)&sh[(rb + 0) * 68 + k4 * 4];
        float4 hv1 = *(const float4*)&sh[(rb + 1) * 68 + k4 * 4];
        float4 hv2 = *(const float4*)&sh[(rb + 2) * 68 + k4 * 4];
        float4 hv3 = *(const float4*)&sh[(rb + 3) * 68 + k4 * 4];
        const float* p0 = &hv0.x;
        const float* p1 = &hv1.x;
        const float* p2 = &hv2.x;
        const float* p3 = &hv3.x;
#pragma unroll
        for (int j = 0; j < 4; j++) {
            int k = k4 * 4 + j;
            ulonglong2 wa = sWu[k * 32 + tx * 2 + 0];
            ulonglong2 wb = sWu[k * 32 + tx * 2 + 1];
            ull H0 = pack2(p0[j]), H1 = pack2(p1[j]), H2 = pack2(p2[j]), H3 = pack2(p3[j]);
            fma2(a0[0], H0, wa.x); fma2(a0[1], H0, wa.y); fma2(a0[2], H0, wb.x); fma2(a0[3], H0, wb.y);
            fma2(a1[0], H1, wa.x); fma2(a1[1], H1, wa.y); fma2(a1[2], H1, wb.x); fma2(a1[3], H1, wb.y);
            fma2(a2[0], H2, wa.x); fma2(a2[1], H2, wa.y); fma2(a2[2], H2, wb.x); fma2(a2[3], H2, wb.y);
            fma2(a3[0], H3, wa.x); fma2(a3[1], H3, wa.y); fma2(a3[2], H3, wb.x); fma2(a3[3], H3, wb.y);
        }
    }
    if (tx < 8) {  // fold bm1 into A half (added exactly once per edge)
        const ulonglong2* bmu = (const ulonglong2*)bm1;
        ulonglong2 ba = bmu[tx * 2 + 0];
        ulonglong2 bb = bmu[tx * 2 + 1];
        a0[0] = add2(a0[0], ba.x); a0[1] = add2(a0[1], ba.y); a0[2] = add2(a0[2], bb.x); a0[3] = add2(a0[3], bb.y);
        a1[0] = add2(a1[0], ba.x); a1[1] = add2(a1[1], ba.y); a1[2] = add2(a1[2], bb.x); a1[3] = add2(a1[3], bb.y);
        a2[0] = add2(a2[0], ba.x); a2[1] = add2(a2[1], ba.y); a2[2] = add2(a2[2], bb.x); a2[3] = add2(a2[3], bb.y);
        a3[0] = add2(a3[0], ba.x); a3[1] = add2(a3[1], ba.y); a3[2] = add2(a3[2], bb.x); a3[3] = add2(a3[3], bb.y);
    }
    uint4* P4 = (uint4*)g_Ph;
    int row = row0 + rb;
    ull* rows[4] = {a0, a1, a2, a3};
#pragma unroll
    for (int rr = 0; rr < 4; rr++) {
        if (row + rr >= N_NODES) break;
        float lo, hi;
        uint4 u;
        unpack2(rows[rr][0], lo, hi); u.x = f2h2(lo, hi);
        unpack2(rows[rr][1], lo, hi); u.y = f2h2(lo, hi);
        unpack2(rows[rr][2], lo, hi); u.z = f2h2(lo, hi);
        unpack2(rows[rr][3], lo, hi); u.w = f2h2(lo, hi);
        P4[(row + rr) * 16 + tx] = u;   // 8 cols starting at 8*tx
    }
}

// per-edge: hidden = relu(A[src] + B[dst] + ea@We); out = sigmoid(hidden . Wm2 + bm2)
// A+B summed in fp16 (1 HADD2 per half2), single conversion of the sum.
__global__ void k_edge(const int* __restrict__ src, const int* __restrict__ dst,
                       const float* __restrict__ ea, const float* __restrict__ Wm1,
                       const float* __restrict__ Wm2, const float* __restrict__ bm2,
                       float* __restrict__ out) {
    __shared__ ull sWe[16 * 32];  // Wm1 rows 128..143: [k][col-pair j2]
    __shared__ float sW2[64];
    __shared__ float sb2;
    int tid = threadIdx.x;
    for (int i = tid; i < 512; i += 256) {
        int k = i >> 5, j2 = i & 31;
        const float2* wrow = (const float2*)(Wm1 + (128 + k) * 64);
        sWe[i] = packf2(wrow[j2]);
    }
    if (tid < 64) sW2[tid] = Wm2[tid];
    if (tid == 0) sb2 = bm2[0];
    __syncthreads();
    unsigned int e = blockIdx.x * blockDim.x + tid;
    if (e >= N_EDGES) return;
    int s = src[e], d = dst[e];
    const uint4* PsA = (const uint4*)(g_Ph + s * 128);        // A half: 8 uint4
    const uint4* PdB = (const uint4*)(g_Ph + d * 128 + 64);   // B half: 8 uint4
    ull ek2[16];
    {
        const float4* ea4 = (const float4*)(ea + (size_t)e * 16);
#pragma unroll
        for (int q = 0; q < 4; q++) {
            float4 v = ea4[q];
            ek2[4 * q + 0] = pack2(v.x); ek2[4 * q + 1] = pack2(v.y);
            ek2[4 * q + 2] = pack2(v.z); ek2[4 * q + 3] = pack2(v.w);
        }
    }
    float acc = 0.f;
#pragma unroll
    for (int jg8 = 0; jg8 < 8; jg8++) {   // 8 cols per iteration
        uint4 au = PsA[jg8];
        uint4 bu = PdB[jg8];
        ull v0 = h2tof2(hadd2(au.x, bu.x));
        ull v1 = h2tof2(hadd2(au.y, bu.y));
        ull v2 = h2tof2(hadd2(au.z, bu.z));
        ull v3 = h2tof2(hadd2(au.w, bu.w));
#pragma unroll
        for (int k = 0; k < 16; k++) {
            const ull* w = &sWe[k * 32 + jg8 * 4];
            fma2(v0, ek2[k], w[0]);
            fma2(v1, ek2[k], w[1]);
            fma2(v2, ek2[k], w[2]);
            fma2(v3, ek2[k], w[3]);
        }
        float f0, f1, f2, f3, f4, f5, f6, f7;
        unpack2(v0, f0, f1); unpack2(v1, f2, f3);
        unpack2(v2, f4, f5); unpack2(v3, f6, f7);
        f0 = fmaxf(f0, 0.f); f1 = fmaxf(f1, 0.f); f2 = fmaxf(f2, 0.f); f3 = fmaxf(f3, 0.f);
        f4 = fmaxf(f4, 0.f); f5 = fmaxf(f5, 0.f); f6 = fmaxf(f6, 0.f); f7 = fmaxf(f7, 0.f);
        const float* w2 = &sW2[jg8 * 8];
        acc += f0 * w2[0] + f1 * w2[1] + f2 * w2[2] + f3 * w2[3]
             + f4 * w2[4] + f5 * w2[5] + f6 * w2[6] + f7 * w2[7];
    }
    out[e] = 1.f / (1.f + __expf(-(acc + sb2)));
}

extern "C" void kernel_launch(void* const* d_in, const int* in_sizes, int n_in,
                              void* d_out, int out_size) {
    const float* x   = (const float*)d_in[0];
    const int*   src = (const int*)d_in[1];
    const int*   dst = (const int*)d_in[2];
    const float* ea  = (const float*)d_in[3];
    const float* W1  = (const float*)d_in[4];
    const float* b1  = (const float*)d_in[5];
    const float* Wm1 = (const float*)d_in[6];
    const float* bm1 = (const float*)d_in[7];
    const float* Wm2 = (const float*)d_in[8];
    const float* bm2 = (const float*)d_in[9];
    float* out = (float*)d_out;
    (void)in_sizes; (void)n_in; (void)out_size;

    const int NB_SCAN = (N_NODES + 1023) / 1024;  // 49

    k_zero<<<(N_NODES + 255) / 256, 256>>>();
    k_mm1cnt<<<MM1_BLOCKS + CNT_BLOCKS, 256>>>(x, W1, dst);
    k_scan1<<<NB_SCAN, 1024>>>();
    k_scan3<<<NB_SCAN, 1024>>>(NB_SCAN);
    k_fill<<<(N_EDGES + 255) / 256, 256>>>(src, dst);
    k_agg<<<(N_NODES * 8 + 255) / 256, 256>>>();
    k_mm2<<<(N_NODES + 63) / 64, 256>>>(Wm1, b1, bm1);
    k_edge<<<(N_EDGES + 255) / 256, 256>>>(src, dst, ea, Wm1, Wm2, bm2, out);
}